// round 15
// baseline (speedup 1.0000x reference)
#include <cuda_runtime.h>
#include <cuda_bf16.h>
#include <cstdint>

// Fixed problem shapes
#define T_TOK  4096
#define DMODEL 1024
#define NEXP   16
#define IEXP   512
#define ISH    2048
#define MAXROWS (2 * T_TOK)

typedef unsigned long long u64;

// ---------------- scratch (device globals; no allocation allowed) ----------
static __device__ int   g_cnt[NEXP];
static __device__ int   g_off[NEXP + 1];
static __device__ int   g_cur[NEXP];
static __device__ int   g_rows[MAXROWS];
static __device__ int   g_slot[T_TOK * 2];
static __device__ int   g_eidx[T_TOK * 2];
static __device__ float g_twt[T_TOK * 2];

// bf16 hi/lo split operands
static __device__ __nv_bfloat16 g_xh[(size_t)T_TOK * DMODEL];
static __device__ __nv_bfloat16 g_xl[(size_t)T_TOK * DMODEL];
static __device__ __nv_bfloat16 g_w13h[(size_t)NEXP * 2 * IEXP * DMODEL];
static __device__ __nv_bfloat16 g_w13l[(size_t)NEXP * 2 * IEXP * DMODEL];
static __device__ __nv_bfloat16 g_w2h[(size_t)NEXP * DMODEL * IEXP];
static __device__ __nv_bfloat16 g_w2l[(size_t)NEXP * DMODEL * IEXP];
static __device__ __nv_bfloat16 g_w13sh[(size_t)2 * ISH * DMODEL];
static __device__ __nv_bfloat16 g_w13sl[(size_t)2 * ISH * DMODEL];
static __device__ __nv_bfloat16 g_w2sh[(size_t)DMODEL * ISH];
static __device__ __nv_bfloat16 g_w2sl[(size_t)DMODEL * ISH];
// activations (hi/lo)
static __device__ __nv_bfloat16 g_acth[(size_t)T_TOK * ISH];
static __device__ __nv_bfloat16 g_actl[(size_t)T_TOK * ISH];
static __device__ __nv_bfloat16 g_arth[(size_t)MAXROWS * IEXP];
static __device__ __nv_bfloat16 g_artl[(size_t)MAXROWS * IEXP];
// routed down-proj output, packed rows (combined later; no atomics)
static __device__ float g_dnout[(size_t)MAXROWS * DMODEL];

// ---------------- PTX helpers ----------------------------------------------
__device__ __forceinline__ uint32_t smem_u32(const void* p) {
    uint32_t a;
    asm("{ .reg .u64 t; cvta.to.shared.u64 t, %1; cvt.u32.u64 %0, t; }" : "=r"(a) : "l"(p));
    return a;
}
__device__ __forceinline__ void cpa16(uint32_t s, const void* g) {
    asm volatile("cp.async.cg.shared.global [%0], [%1], 16;" :: "r"(s), "l"(g) : "memory");
}
__device__ __forceinline__ void cpa_commit() {
    asm volatile("cp.async.commit_group;" ::: "memory");
}
template <int N>
__device__ __forceinline__ void cpa_wait() {
    asm volatile("cp.async.wait_group %0;" :: "n"(N) : "memory");
}
__device__ __forceinline__ void ldsm4(uint32_t* r, uint32_t addr) {
    asm volatile("ldmatrix.sync.aligned.m8n8.x4.shared.b16 {%0,%1,%2,%3}, [%4];"
        : "=r"(r[0]), "=r"(r[1]), "=r"(r[2]), "=r"(r[3]) : "r"(addr));
}
__device__ __forceinline__ void mma16816(float* d, const uint32_t* a, const uint32_t* b) {
    asm volatile(
        "mma.sync.aligned.m16n8k16.row.col.f32.bf16.bf16.f32 "
        "{%0,%1,%2,%3}, {%4,%5,%6,%7}, {%8,%9}, {%0,%1,%2,%3};"
        : "+f"(d[0]), "+f"(d[1]), "+f"(d[2]), "+f"(d[3])
        : "r"(a[0]), "r"(a[1]), "r"(a[2]), "r"(a[3]), "r"(b[0]), "r"(b[1]));
}
// swizzle for 64-byte rows (32 bf16), period-8: XOR 16B-chunk bits with row&7
__device__ __forceinline__ uint32_t swz64(uint32_t bo) {
    return bo ^ (((bo >> 6) & 7) << 4);
}
__device__ __forceinline__ float silu(float x) { return x / (1.0f + __expf(-x)); }

// ---------------- small kernels -------------------------------------------
__global__ void k_init() {
    if (threadIdx.x < NEXP) g_cnt[threadIdx.x] = 0;
}

__global__ void k_router(const float* __restrict__ logits) {
    int t = blockIdx.x * blockDim.x + threadIdx.x;
    if (t >= T_TOK) return;
    const float* l = logits + (size_t)t * NEXP;
    float m1 = -3.4e38f, m2 = -3.4e38f;
    int i1 = 0, i2 = 0;
#pragma unroll
    for (int e = 0; e < NEXP; e++) {
        float v = l[e];
        if (v > m1) { m2 = m1; i2 = i1; m1 = v; i1 = e; }
        else if (v > m2) { m2 = v; i2 = e; }
    }
    float r   = expf(m2 - m1);
    float w2v = r / (1.0f + r);
    float w1v = 1.0f - w2v;
    g_eidx[t * 2 + 0] = i1; g_eidx[t * 2 + 1] = i2;
    g_twt [t * 2 + 0] = w1v; g_twt[t * 2 + 1] = w2v;
    atomicAdd(&g_cnt[i1], 1);
    atomicAdd(&g_cnt[i2], 1);
}

__global__ void k_prefix() {
    if (threadIdx.x == 0) {
        int s = 0;
        for (int e = 0; e < NEXP; e++) { g_off[e] = s; g_cur[e] = s; s += g_cnt[e]; }
        g_off[NEXP] = s;
    }
}

__global__ void k_scatter() {
    int t = blockIdx.x * blockDim.x + threadIdx.x;
    if (t >= T_TOK) return;
#pragma unroll
    for (int k = 0; k < 2; k++) {
        int e = g_eidx[t * 2 + k];
        int pos = atomicAdd(&g_cur[e], 1);
        g_rows[pos] = t;
        g_slot[t * 2 + k] = pos;
    }
}

// fp32 -> bf16 hi/lo split (vectorized)
__global__ void k_cvt4(const float4* __restrict__ s, uint2* __restrict__ h,
                       uint2* __restrict__ l, int n4) {
    int i = blockIdx.x * blockDim.x + threadIdx.x;
    if (i >= n4) return;
    float4 v = s[i];
    __nv_bfloat16 h0 = __float2bfloat16(v.x), h1 = __float2bfloat16(v.y);
    __nv_bfloat16 h2 = __float2bfloat16(v.z), h3 = __float2bfloat16(v.w);
    __nv_bfloat16 l0 = __float2bfloat16(v.x - __bfloat162float(h0));
    __nv_bfloat16 l1 = __float2bfloat16(v.y - __bfloat162float(h1));
    __nv_bfloat16 l2 = __float2bfloat16(v.z - __bfloat162float(h2));
    __nv_bfloat16 l3 = __float2bfloat16(v.w - __bfloat162float(h3));
    __nv_bfloat162 hp0{h0, h1}, hp1{h2, h3}, lp0{l0, l1}, lp1{l2, l3};
    uint2 hh, ll;
    hh.x = *(uint32_t*)&hp0; hh.y = *(uint32_t*)&hp1;
    ll.x = *(uint32_t*)&lp0; ll.y = *(uint32_t*)&lp1;
    h[i] = hh; l[i] = ll;
}

// combine: fused_out[t] = w0 * dnout[slot0(t)] + w1 * dnout[slot1(t)]
__global__ void k_combine(float* __restrict__ fo) {
    int i = blockIdx.x * blockDim.x + threadIdx.x;
    if (i >= T_TOK * DMODEL / 4) return;
    int t = i / (DMODEL / 4);
    int c = (i % (DMODEL / 4)) * 4;
    float w0 = g_twt[2 * t], w1 = g_twt[2 * t + 1];
    const float4 a = *(const float4*)&g_dnout[(size_t)g_slot[2 * t]     * DMODEL + c];
    const float4 b = *(const float4*)&g_dnout[(size_t)g_slot[2 * t + 1] * DMODEL + c];
    float4 r;
    r.x = w0 * a.x + w1 * b.x;
    r.y = w0 * a.y + w1 * b.y;
    r.z = w0 * a.z + w1 * b.z;
    r.w = w0 * a.w + w1 * b.w;
    *(float4*)&fo[(size_t)t * DMODEL + c] = r;
}

// ---------------- SwiGLU HMMA GEMM (K32 3-buffer ring, 1 sync/stage, occ 2) -
// Block: 128 token rows x 64 gate + 64 up cols. K-stage 32.
// Stage layout (32KB): Ah 8K | Al 8K | Gh 4K | Gl 4K | Uh 4K | Ul 4K.
// Ring of 3 stages: wait<1> leaves next stage's loads in flight (no drain);
// ONE __syncthreads per stage publishes loads + protects buffer reuse.
#define SW_SMEM 98304      // 3 x 32K mainloop; epilogue ~70.6K fits
template <bool ROUTED>
__global__ __launch_bounds__(256, 2) void k_swiglu_mma() {
    extern __shared__ char smem[];
    const int NI = ROUTED ? IEXP : ISH;
    int r0, r1;
    const __nv_bfloat16 *Wh, *Wl;
    if (ROUTED) {
        int e = blockIdx.x >> 5, mt = blockIdx.x & 31;
        r0 = g_off[e] + mt * 128;
        int re = g_off[e + 1];
        if (r0 >= re) return;
        r1 = min(re, r0 + 128);
        Wh = g_w13h + (size_t)e * 2 * IEXP * DMODEL;
        Wl = g_w13l + (size_t)e * 2 * IEXP * DMODEL;
    } else {
        r0 = blockIdx.x * 128; r1 = r0 + 128;
        Wh = g_w13sh; Wl = g_w13sl;
    }
    const int n0  = blockIdx.y * 64;
    const int tid = threadIdx.x, wid = tid >> 5, lid = tid & 31;
    const int wm = wid & 3, isup = wid >> 2;
    uint32_t sb = smem_u32(smem);
    const __nv_bfloat16 *Xh = g_xh, *Xl = g_xl;

    // loader precompute — A: rows (tid>>2), (tid>>2)+64; v = tid&3 (16B cols)
    const int roA = tid >> 2, vA = tid & 3;
    uint32_t soA[2], aof[2];
#pragma unroll
    for (int j = 0; j < 2; j++) {
        int rr = roA + 64 * j;
        soA[j] = swz64((uint32_t)(rr * 64 + vA * 16));
        int ar = r0 + rr;
        if (ROUTED) ar = g_rows[min(ar, r1 - 1)];
        aof[j] = (uint32_t)(ar * DMODEL + vA * 8);
    }
    // B: threads 0-127 gate, 128-255 up; rows (tb>>2), (tb>>2)+32; v = tb&3
    const int half = tid >> 7, tb_ = tid & 127;
    const int roB = tb_ >> 2, vB = tb_ & 3;
    const uint32_t bOffH = 16384 + half * 8192;   // Gh or Uh
    uint32_t soB[2], bof[2];
#pragma unroll
    for (int j = 0; j < 2; j++) {
        int rr = roB + 32 * j;
        soB[j] = swz64((uint32_t)(rr * 64 + vB * 16));
        bof[j] = (uint32_t)((half * NI + n0 + rr) * DMODEL + vB * 8);
    }

    float acc[2][8][4];
#pragma unroll
    for (int a = 0; a < 2; a++)
#pragma unroll
        for (int b = 0; b < 8; b++)
#pragma unroll
            for (int c = 0; c < 4; c++) acc[a][b][c] = 0.0f;

    const int S = DMODEL / 32;   // 32

#define SW_ISSUE(tbase, stg)                                                   \
    {                                                                          \
        uint32_t tb = (tbase);                                                 \
        int kof = (stg) * 32;                                                  \
        _Pragma("unroll")                                                      \
        for (int j = 0; j < 2; j++) {                                          \
            cpa16(tb +    0 + soA[j], Xh + aof[j] + kof);                      \
            cpa16(tb + 8192 + soA[j], Xl + aof[j] + kof);                      \
        }                                                                      \
        _Pragma("unroll")                                                      \
        for (int j = 0; j < 2; j++) {                                          \
            cpa16(tb + bOffH +        soB[j], Wh + bof[j] + kof);              \
            cpa16(tb + bOffH + 4096 + soB[j], Wl + bof[j] + kof);              \
        }                                                                      \
        cpa_commit();                                                          \
    }

    SW_ISSUE(sb, 0);
    SW_ISSUE(sb + 32768, 1);
    int bi = 0;   // ring slot of stage s
    for (int s = 0; s < S; s++) {
        if (s + 2 < S) cpa_wait<1>();   // stage s landed; s+1 may be in flight
        else           cpa_wait<0>();   // tail: everything must land
        __syncthreads();                // publish loads + all warps past compute(s-1)
        if (s + 2 < S) {
            int b2 = bi + 2; if (b2 >= 3) b2 -= 3;
            SW_ISSUE(sb + b2 * 32768, s + 2);   // buffer last used at compute(s-1): safe
        }
        uint32_t tb = sb + bi * 32768;
        uint32_t sA = tb;
        uint32_t sG = tb + 16384 + isup * 8192;
#pragma unroll
        for (int ks = 0; ks < 2; ks++) {
            int kb2 = ks * 32;
            uint32_t ah[2][4], al[2][4];
#pragma unroll
            for (int mt = 0; mt < 2; mt++) {
                int row = wm * 32 + mt * 16 + (lid & 15);
                uint32_t bo = (uint32_t)(row * 64 + kb2 + ((lid >> 4) << 4));
                uint32_t ad = sA + (bo ^ ((row & 7) << 4));
                ldsm4(ah[mt], ad);
                ldsm4(al[mt], ad + 8192);
            }
#pragma unroll
            for (int ng = 0; ng < 4; ng++) {
                int nrow = ng * 16 + (lid & 7) + ((lid >> 4) << 3);
                uint32_t bo = (uint32_t)(nrow * 64 + kb2 + (((lid >> 3) & 1) << 4));
                uint32_t ad = sG + (bo ^ ((nrow & 7) << 4));
                uint32_t bh[4], bl[4];
                ldsm4(bh, ad);
                ldsm4(bl, ad + 4096);
#pragma unroll
                for (int mt = 0; mt < 2; mt++)
#pragma unroll
                    for (int p = 0; p < 2; p++) {
                        int nt = ng * 2 + p;
                        mma16816(acc[mt][nt], ah[mt], bh + 2 * p);
                        mma16816(acc[mt][nt], ah[mt], bl + 2 * p);
                        mma16816(acc[mt][nt], al[mt], bh + 2 * p);
                    }
            }
        }
        if (++bi == 3) bi = 0;
    }
#undef SW_ISSUE
    __syncthreads();   // before smem reuse in epilogue

    // epilogue: up warps stash U to smem; gate warps combine silu(g)*u
    float* u_s = (float*)smem;                            // [128][66]
    __nv_bfloat16* h_s = (__nv_bfloat16*)(smem + 34816);  // [128][72]
    __nv_bfloat16* l_s = (__nv_bfloat16*)(smem + 53248);  // [128][72]
    if (isup) {
#pragma unroll
        for (int mt = 0; mt < 2; mt++)
#pragma unroll
            for (int nt = 0; nt < 8; nt++) {
                int r_ = wm * 32 + mt * 16 + (lid >> 2);
                int c_ = nt * 8 + 2 * (lid & 3);
                *(float2*)&u_s[r_ * 66 + c_]       = make_float2(acc[mt][nt][0], acc[mt][nt][1]);
                *(float2*)&u_s[(r_ + 8) * 66 + c_] = make_float2(acc[mt][nt][2], acc[mt][nt][3]);
            }
    }
    __syncthreads();
    if (!isup) {
#pragma unroll
        for (int mt = 0; mt < 2; mt++)
#pragma unroll
            for (int nt = 0; nt < 8; nt++) {
                int r_ = wm * 32 + mt * 16 + (lid >> 2);
                int c_ = nt * 8 + 2 * (lid & 3);
#pragma unroll
                for (int hh = 0; hh < 2; hh++) {
                    int rr = r_ + hh * 8;
                    float2 u = *(float2*)&u_s[rr * 66 + c_];
                    float o0 = silu(acc[mt][nt][2 * hh + 0]) * u.x;
                    float o1 = silu(acc[mt][nt][2 * hh + 1]) * u.y;
                    __nv_bfloat16 h0 = __float2bfloat16(o0), h1 = __float2bfloat16(o1);
                    __nv_bfloat16 q0 = __float2bfloat16(o0 - __bfloat162float(h0));
                    __nv_bfloat16 q1 = __float2bfloat16(o1 - __bfloat162float(h1));
                    __nv_bfloat162 hp{h0, h1}, lp{q0, q1};
                    *(uint32_t*)&h_s[rr * 72 + c_] = *(uint32_t*)&hp;
                    *(uint32_t*)&l_s[rr * 72 + c_] = *(uint32_t*)&lp;
                }
            }
    }
    __syncthreads();
    __nv_bfloat16* AH = ROUTED ? g_arth : g_acth;
    __nv_bfloat16* AL = ROUTED ? g_artl : g_actl;
    for (int i = tid; i < 128 * 8; i += 256) {
        int row = i >> 3, vv = i & 7;
        if (ROUTED && r0 + row >= r1) continue;
        *(uint4*)(AH + (size_t)(r0 + row) * NI + n0 + vv * 8) = *(uint4*)(h_s + row * 72 + vv * 8);
        *(uint4*)(AL + (size_t)(r0 + row) * NI + n0 + vv * 8) = *(uint4*)(l_s + row * 72 + vv * 8);
    }
}

// ---------------- Down-proj HMMA GEMM (K32 3-buffer ring, occ 2) ------------
// Block: 128 rows x 128 cols. Stage (32KB): Ah 8K | Al 8K | Bh 8K | Bl 8K.
#define DN_SMEM 98304      // 3 x 32K mainloop; epilogue 67.6K fits
template <bool ROUTED>
__global__ __launch_bounds__(256, 2) void k_down_mma(float* __restrict__ OUT) {
    extern __shared__ char smem[];
    const int KI = ROUTED ? IEXP : ISH;
    const __nv_bfloat16* AHs = ROUTED ? g_arth : g_acth;
    const __nv_bfloat16* ALs = ROUTED ? g_artl : g_actl;
    int r0, r1;
    const __nv_bfloat16 *Wh, *Wl;
    if (ROUTED) {
        int e = blockIdx.x >> 5, mt = blockIdx.x & 31;
        r0 = g_off[e] + mt * 128;
        int re = g_off[e + 1];
        if (r0 >= re) return;
        r1 = min(re, r0 + 128);
        Wh = g_w2h + (size_t)e * DMODEL * IEXP;
        Wl = g_w2l + (size_t)e * DMODEL * IEXP;
    } else {
        r0 = blockIdx.x * 128; r1 = r0 + 128;
        Wh = g_w2sh; Wl = g_w2sl;
    }
    const int n0  = blockIdx.y * 128;
    const int tid = threadIdx.x, wid = tid >> 5, lid = tid & 31;
    const int wm = wid & 3, wn = wid >> 2;
    uint32_t sb = smem_u32(smem);

    const int ro = tid >> 2, vv_ = tid & 3;
    uint32_t so[2], aof[2], bof[2];
#pragma unroll
    for (int j = 0; j < 2; j++) {
        int rr = ro + 64 * j;
        so[j]  = swz64((uint32_t)(rr * 64 + vv_ * 16));
        aof[j] = (uint32_t)(min(r0 + rr, r1 - 1) * KI + vv_ * 8);
        bof[j] = (uint32_t)((n0 + rr) * KI + vv_ * 8);
    }

    float acc[2][8][4];
#pragma unroll
    for (int a = 0; a < 2; a++)
#pragma unroll
        for (int b = 0; b < 8; b++)
#pragma unroll
            for (int c = 0; c < 4; c++) acc[a][b][c] = 0.0f;

    const int S = KI / 32;

#define DN_ISSUE(tbase, stg)                                                   \
    {                                                                          \
        uint32_t tb = (tbase);                                                 \
        int kof = (stg) * 32;                                                  \
        _Pragma("unroll")                                                      \
        for (int j = 0; j < 2; j++) {                                          \
            cpa16(tb +     0 + so[j], AHs + aof[j] + kof);                     \
            cpa16(tb +  8192 + so[j], ALs + aof[j] + kof);                     \
            cpa16(tb + 16384 + so[j], Wh + bof[j] + kof);                      \
            cpa16(tb + 24576 + so[j], Wl + bof[j] + kof);                      \
        }                                                                      \
        cpa_commit();                                                          \
    }

    DN_ISSUE(sb, 0);
    DN_ISSUE(sb + 32768, 1);
    int bi = 0;
    for (int s = 0; s < S; s++) {
        if (s + 2 < S) cpa_wait<1>();
        else           cpa_wait<0>();
        __syncthreads();
        if (s + 2 < S) {
            int b2 = bi + 2; if (b2 >= 3) b2 -= 3;
            DN_ISSUE(sb + b2 * 32768, s + 2);
        }
        uint32_t tb = sb + bi * 32768;
        uint32_t sA = tb, sBb = tb + 16384;
#pragma unroll
        for (int ks = 0; ks < 2; ks++) {
            int kb2 = ks * 32;
            uint32_t ah[2][4], al[2][4];
#pragma unroll
            for (int mt = 0; mt < 2; mt++) {
                int row = wm * 32 + mt * 16 + (lid & 15);
                uint32_t bo = (uint32_t)(row * 64 + kb2 + ((lid >> 4) << 4));
                uint32_t ad = sA + (bo ^ ((row & 7) << 4));
                ldsm4(ah[mt], ad);
                ldsm4(al[mt], ad + 8192);
            }
#pragma unroll
            for (int ng = 0; ng < 4; ng++) {
                int nrow = wn * 64 + ng * 16 + (lid & 7) + ((lid >> 4) << 3);
                uint32_t bo = (uint32_t)(nrow * 64 + kb2 + (((lid >> 3) & 1) << 4));
                uint32_t ad = sBb + (bo ^ ((nrow & 7) << 4));
                uint32_t bh[4], bl[4];
                ldsm4(bh, ad);
                ldsm4(bl, ad + 8192);
#pragma unroll
                for (int mt = 0; mt < 2; mt++)
#pragma unroll
                    for (int p = 0; p < 2; p++) {
                        int nt = ng * 2 + p;
                        mma16816(acc[mt][nt], ah[mt], bh + 2 * p);
                        mma16816(acc[mt][nt], ah[mt], bl + 2 * p);
                        mma16816(acc[mt][nt], al[mt], bh + 2 * p);
                    }
            }
        }
        if (++bi == 3) bi = 0;
    }
#undef DN_ISSUE
    __syncthreads();

    // epilogue via smem f32 tile [128][132]
    float* c_s = (float*)smem;
#pragma unroll
    for (int mt = 0; mt < 2; mt++)
#pragma unroll
        for (int nt = 0; nt < 8; nt++) {
            int r_ = wm * 32 + mt * 16 + (lid >> 2);
            int c_ = wn * 64 + nt * 8 + 2 * (lid & 3);
            *(float2*)&c_s[r_ * 132 + c_]       = make_float2(acc[mt][nt][0], acc[mt][nt][1]);
            *(float2*)&c_s[(r_ + 8) * 132 + c_] = make_float2(acc[mt][nt][2], acc[mt][nt][3]);
        }
    __syncthreads();
    if (!ROUTED) {
        for (int i = tid; i < 128 * 32; i += 256) {
            int row = i >> 5, vv = i & 31;
            *(float4*)(OUT + (size_t)(r0 + row) * DMODEL + n0 + vv * 4) =
                *(float4*)(c_s + row * 132 + vv * 4);
        }
    } else {
        for (int i = tid; i < 128 * 32; i += 256) {
            int row = i >> 5, vv = i & 31;
            if (r0 + row < r1)
                *(float4*)(g_dnout + (size_t)(r0 + row) * DMODEL + n0 + vv * 4) =
                    *(float4*)(c_s + row * 132 + vv * 4);
        }
    }
}

// ---------------- launch ---------------------------------------------------
extern "C" void kernel_launch(void* const* d_in, const int* in_sizes, int n_in,
                              void* d_out, int out_size) {
    const float* x      = (const float*)d_in[0];
    const float* logits = (const float*)d_in[1];
    const float* w13    = (const float*)d_in[2];
    const float* w2     = (const float*)d_in[3];
    const float* w13s   = (const float*)d_in[4];
    const float* w2s    = (const float*)d_in[5];
    float* out = (float*)d_out;
    float* shared_out = out;
    float* fused_out  = out + (size_t)T_TOK * DMODEL;

    static cudaStream_t sB = nullptr;
    static cudaEvent_t evX = nullptr, evJoin = nullptr;
    if (!sB) {
        cudaStreamCreateWithFlags(&sB, cudaStreamNonBlocking);
        cudaEventCreateWithFlags(&evX, cudaEventDisableTiming);
        cudaEventCreateWithFlags(&evJoin, cudaEventDisableTiming);
        cudaFuncSetAttribute(k_swiglu_mma<false>, cudaFuncAttributeMaxDynamicSharedMemorySize, SW_SMEM);
        cudaFuncSetAttribute(k_swiglu_mma<true>,  cudaFuncAttributeMaxDynamicSharedMemorySize, SW_SMEM);
        cudaFuncSetAttribute(k_down_mma<false>,   cudaFuncAttributeMaxDynamicSharedMemorySize, DN_SMEM);
        cudaFuncSetAttribute(k_down_mma<true>,    cudaFuncAttributeMaxDynamicSharedMemorySize, DN_SMEM);
    }

    __nv_bfloat16 *xh, *xl, *w13h, *w13l, *w2h, *w2l, *w13sh, *w13sl, *w2sh, *w2sl;
    cudaGetSymbolAddress((void**)&xh, g_xh);   cudaGetSymbolAddress((void**)&xl, g_xl);
    cudaGetSymbolAddress((void**)&w13h, g_w13h); cudaGetSymbolAddress((void**)&w13l, g_w13l);
    cudaGetSymbolAddress((void**)&w2h, g_w2h);   cudaGetSymbolAddress((void**)&w2l, g_w2l);
    cudaGetSymbolAddress((void**)&w13sh, g_w13sh); cudaGetSymbolAddress((void**)&w13sl, g_w13sl);
    cudaGetSymbolAddress((void**)&w2sh, g_w2sh);   cudaGetSymbolAddress((void**)&w2sl, g_w2sl);

    auto cvt = [](cudaStream_t st, const float* src, __nv_bfloat16* h, __nv_bfloat16* l, int n) {
        int n4 = n / 4;
        k_cvt4<<<(n4 + 255) / 256, 256, 0, st>>>((const float4*)src, (uint2*)h, (uint2*)l, n4);
    };

    // ---- stream A: shared-expert path -------------------------------------
    cvt(0, x, xh, xl, T_TOK * DMODEL);              // launch 0
    cudaEventRecord(evX, 0);                        // fork: B only needs x
    cvt(0, w13s, w13sh, w13sl, 2 * ISH * DMODEL);   // launch 1
    cvt(0, w2s,  w2sh,  w2sl,  DMODEL * ISH);       // launch 2
    {
        dim3 g(T_TOK / 128, ISH / 64);              // launch 3 — ncu target
        k_swiglu_mma<false><<<g, 256, SW_SMEM>>>();
    }

    // ---- stream B: routing + routed path (overlaps swiglu_sh) -------------
    cudaStreamWaitEvent(sB, evX, 0);
    k_init<<<1, 32, 0, sB>>>();
    k_router<<<(T_TOK + 255) / 256, 256, 0, sB>>>(logits);
    k_prefix<<<1, 32, 0, sB>>>();
    k_scatter<<<(T_TOK + 255) / 256, 256, 0, sB>>>();
    cvt(sB, w13, w13h, w13l, NEXP * 2 * IEXP * DMODEL);
    cvt(sB, w2,  w2h,  w2l,  NEXP * DMODEL * IEXP);
    {
        dim3 g(NEXP * 32, IEXP / 64);
        k_swiglu_mma<true><<<g, 256, SW_SMEM, sB>>>();
    }
    {
        dim3 g(NEXP * 32, DMODEL / 128);
        k_down_mma<true><<<g, 256, DN_SMEM, sB>>>(nullptr);
    }
    k_combine<<<(T_TOK * DMODEL / 4 + 255) / 256, 256, 0, sB>>>(fused_out);
    cudaEventRecord(evJoin, sB);

    // ---- stream A continues: shared down-proj ------------------------------
    {
        dim3 g(T_TOK / 128, DMODEL / 128);
        k_down_mma<false><<<g, 256, DN_SMEM>>>(shared_out);
    }
    cudaStreamWaitEvent(0, evJoin, 0);
}

// round 16
// speedup vs baseline: 1.4333x; 1.4333x over previous
#include <cuda_runtime.h>
#include <cuda_fp16.h>
#include <cstdint>

// Fixed problem shapes
#define T_TOK  4096
#define DMODEL 1024
#define NEXP   16
#define IEXP   512
#define ISH    2048
#define MAXROWS (2 * T_TOK)

typedef unsigned long long u64;

// ---------------- scratch (device globals; no allocation allowed) ----------
static __device__ int   g_cnt[NEXP];
static __device__ int   g_off[NEXP + 1];
static __device__ int   g_cur[NEXP];
static __device__ int   g_rows[MAXROWS];
static __device__ int   g_slot[T_TOK * 2];
static __device__ int   g_eidx[T_TOK * 2];
static __device__ float g_twt[T_TOK * 2];

// fp16 operands: x/activations split hi+lo; weights truncated hi-only
static __device__ __half g_xh[(size_t)T_TOK * DMODEL];
static __device__ __half g_xl[(size_t)T_TOK * DMODEL];
static __device__ __half g_w13h[(size_t)NEXP * 2 * IEXP * DMODEL];
static __device__ __half g_w2h[(size_t)NEXP * DMODEL * IEXP];
static __device__ __half g_w13sh[(size_t)2 * ISH * DMODEL];
static __device__ __half g_w2sh[(size_t)DMODEL * ISH];
// activations (hi/lo)
static __device__ __half g_acth[(size_t)T_TOK * ISH];
static __device__ __half g_actl[(size_t)T_TOK * ISH];
static __device__ __half g_arth[(size_t)MAXROWS * IEXP];
static __device__ __half g_artl[(size_t)MAXROWS * IEXP];
// routed down-proj output, packed rows (combined later; no atomics)
static __device__ float g_dnout[(size_t)MAXROWS * DMODEL];

// ---------------- PTX helpers ----------------------------------------------
__device__ __forceinline__ uint32_t smem_u32(const void* p) {
    uint32_t a;
    asm("{ .reg .u64 t; cvta.to.shared.u64 t, %1; cvt.u32.u64 %0, t; }" : "=r"(a) : "l"(p));
    return a;
}
__device__ __forceinline__ void cpa16(uint32_t s, const void* g) {
    asm volatile("cp.async.cg.shared.global [%0], [%1], 16;" :: "r"(s), "l"(g) : "memory");
}
__device__ __forceinline__ void cpa_commit() {
    asm volatile("cp.async.commit_group;" ::: "memory");
}
template <int N>
__device__ __forceinline__ void cpa_wait() {
    asm volatile("cp.async.wait_group %0;" :: "n"(N) : "memory");
}
__device__ __forceinline__ void ldsm4(uint32_t* r, uint32_t addr) {
    asm volatile("ldmatrix.sync.aligned.m8n8.x4.shared.b16 {%0,%1,%2,%3}, [%4];"
        : "=r"(r[0]), "=r"(r[1]), "=r"(r[2]), "=r"(r[3]) : "r"(addr));
}
// fp16 MMA, fp32 accumulate
__device__ __forceinline__ void mma16816(float* d, const uint32_t* a, const uint32_t* b) {
    asm volatile(
        "mma.sync.aligned.m16n8k16.row.col.f32.f16.f16.f32 "
        "{%0,%1,%2,%3}, {%4,%5,%6,%7}, {%8,%9}, {%0,%1,%2,%3};"
        : "+f"(d[0]), "+f"(d[1]), "+f"(d[2]), "+f"(d[3])
        : "r"(a[0]), "r"(a[1]), "r"(a[2]), "r"(a[3]), "r"(b[0]), "r"(b[1]));
}
__device__ __forceinline__ uint32_t swz(uint32_t bo) { return bo ^ ((bo >> 3) & 0x70); }
__device__ __forceinline__ float silu(float x) { return x / (1.0f + __expf(-x)); }

// ---------------- small kernels -------------------------------------------
__global__ void k_init() {
    if (threadIdx.x < NEXP) g_cnt[threadIdx.x] = 0;
}

__global__ void k_router(const float* __restrict__ logits) {
    int t = blockIdx.x * blockDim.x + threadIdx.x;
    if (t >= T_TOK) return;
    const float* l = logits + (size_t)t * NEXP;
    float m1 = -3.4e38f, m2 = -3.4e38f;
    int i1 = 0, i2 = 0;
#pragma unroll
    for (int e = 0; e < NEXP; e++) {
        float v = l[e];
        if (v > m1) { m2 = m1; i2 = i1; m1 = v; i1 = e; }
        else if (v > m2) { m2 = v; i2 = e; }
    }
    float r   = expf(m2 - m1);
    float w2v = r / (1.0f + r);
    float w1v = 1.0f - w2v;
    g_eidx[t * 2 + 0] = i1; g_eidx[t * 2 + 1] = i2;
    g_twt [t * 2 + 0] = w1v; g_twt[t * 2 + 1] = w2v;
    atomicAdd(&g_cnt[i1], 1);
    atomicAdd(&g_cnt[i2], 1);
}

__global__ void k_prefix() {
    if (threadIdx.x == 0) {
        int s = 0;
        for (int e = 0; e < NEXP; e++) { g_off[e] = s; g_cur[e] = s; s += g_cnt[e]; }
        g_off[NEXP] = s;
    }
}

__global__ void k_scatter() {
    int t = blockIdx.x * blockDim.x + threadIdx.x;
    if (t >= T_TOK) return;
#pragma unroll
    for (int k = 0; k < 2; k++) {
        int e = g_eidx[t * 2 + k];
        int pos = atomicAdd(&g_cur[e], 1);
        g_rows[pos] = t;
        g_slot[t * 2 + k] = pos;
    }
}

// fp32 -> fp16 hi/lo split (for x)
__global__ void k_cvtHL(const float4* __restrict__ s, uint2* __restrict__ h,
                        uint2* __restrict__ l, int n4) {
    int i = blockIdx.x * blockDim.x + threadIdx.x;
    if (i >= n4) return;
    float4 v = s[i];
    __half h0 = __float2half_rn(v.x), h1 = __float2half_rn(v.y);
    __half h2 = __float2half_rn(v.z), h3 = __float2half_rn(v.w);
    __half l0 = __float2half_rn(v.x - __half2float(h0));
    __half l1 = __float2half_rn(v.y - __half2float(h1));
    __half l2 = __float2half_rn(v.z - __half2float(h2));
    __half l3 = __float2half_rn(v.w - __half2float(h3));
    __half2 hp0{h0, h1}, hp1{h2, h3}, lp0{l0, l1}, lp1{l2, l3};
    uint2 hh, ll;
    hh.x = *(uint32_t*)&hp0; hh.y = *(uint32_t*)&hp1;
    ll.x = *(uint32_t*)&lp0; ll.y = *(uint32_t*)&lp1;
    h[i] = hh; l[i] = ll;
}

// fp32 -> fp16 truncate-only (for weights)
__global__ void k_cvtH(const float4* __restrict__ s, uint2* __restrict__ h, int n4) {
    int i = blockIdx.x * blockDim.x + threadIdx.x;
    if (i >= n4) return;
    float4 v = s[i];
    __half2 hp0{__float2half_rn(v.x), __float2half_rn(v.y)};
    __half2 hp1{__float2half_rn(v.z), __float2half_rn(v.w)};
    uint2 hh;
    hh.x = *(uint32_t*)&hp0; hh.y = *(uint32_t*)&hp1;
    h[i] = hh;
}

// combine: fused_out[t] = w0 * dnout[slot0(t)] + w1 * dnout[slot1(t)]
__global__ void k_combine(float* __restrict__ fo) {
    int i = blockIdx.x * blockDim.x + threadIdx.x;
    if (i >= T_TOK * DMODEL / 4) return;
    int t = i / (DMODEL / 4);
    int c = (i % (DMODEL / 4)) * 4;
    float w0 = g_twt[2 * t], w1 = g_twt[2 * t + 1];
    const float4 a = *(const float4*)&g_dnout[(size_t)g_slot[2 * t]     * DMODEL + c];
    const float4 b = *(const float4*)&g_dnout[(size_t)g_slot[2 * t + 1] * DMODEL + c];
    float4 r;
    r.x = w0 * a.x + w1 * b.x;
    r.y = w0 * a.y + w1 * b.y;
    r.z = w0 * a.z + w1 * b.z;
    r.w = w0 * a.w + w1 * b.w;
    *(float4*)&fo[(size_t)t * DMODEL + c] = r;
}

// ---------------- SwiGLU HMMA GEMM (fp16 2-pass, single-buffer, occ 2) ------
// Block: 128 token rows x 64 gate + 64 up cols. K-stage 64.
// Stage (48KB): Ah 16K | Al 16K | G 8K | U 8K. 2 passes: Ah*B + Al*B.
#define SW_SMEM 73728      // mainloop 48K; epilogue ~70.6K
template <bool ROUTED>
__global__ __launch_bounds__(256, 2) void k_swiglu_mma() {
    extern __shared__ char smem[];
    const int NI = ROUTED ? IEXP : ISH;
    int r0, r1;
    const __half* W;
    if (ROUTED) {
        int e = blockIdx.x >> 5, mt = blockIdx.x & 31;
        r0 = g_off[e] + mt * 128;
        int re = g_off[e + 1];
        if (r0 >= re) return;
        r1 = min(re, r0 + 128);
        W = g_w13h + (size_t)e * 2 * IEXP * DMODEL;
    } else {
        r0 = blockIdx.x * 128; r1 = r0 + 128;
        W = g_w13sh;
    }
    const int n0  = blockIdx.y * 64;
    const int tid = threadIdx.x, wid = tid >> 5, lid = tid & 31;
    const int wm = wid & 3, isup = wid >> 2;
    uint32_t sb = smem_u32(smem);
    const __half *Xh = g_xh, *Xl = g_xl;

    // loader precompute: 128-byte rows (64 f16), same swizzle family as R13
    const int lrow = tid >> 3, v = tid & 7;
    uint32_t soA[4], aof[4];
#pragma unroll
    for (int j = 0; j < 4; j++) {
        int rr = lrow + 32 * j;
        soA[j] = swz((uint32_t)(rr * 128 + v * 16));
        int ar = r0 + rr;
        if (ROUTED) ar = g_rows[min(ar, r1 - 1)];
        aof[j] = (uint32_t)(ar * DMODEL + v * 8);
    }
    uint32_t soB[2], gof[2], uof[2];
#pragma unroll
    for (int j = 0; j < 2; j++) {
        int rr = lrow + 32 * j;
        soB[j] = swz((uint32_t)(rr * 128 + v * 16));
        gof[j] = (uint32_t)((n0 + rr) * DMODEL + v * 8);
        uof[j] = (uint32_t)((NI + n0 + rr) * DMODEL + v * 8);
    }

    float acc[2][8][4];
#pragma unroll
    for (int a = 0; a < 2; a++)
#pragma unroll
        for (int b = 0; b < 8; b++)
#pragma unroll
            for (int c = 0; c < 4; c++) acc[a][b][c] = 0.0f;

    const int S = DMODEL / 64;   // 16
    for (int s = 0; s < S; s++) {
        int kof = s * 64;
#pragma unroll
        for (int j = 0; j < 4; j++) {
            cpa16(sb +     0 + soA[j], Xh + aof[j] + kof);
            cpa16(sb + 16384 + soA[j], Xl + aof[j] + kof);
        }
#pragma unroll
        for (int j = 0; j < 2; j++) {
            cpa16(sb + 32768 + soB[j], W + gof[j] + kof);
            cpa16(sb + 40960 + soB[j], W + uof[j] + kof);
        }
        cpa_commit();
        cpa_wait<0>();
        __syncthreads();          // buffer filled, visible to all warps
        uint32_t sA = sb;
        uint32_t sBb = sb + 32768 + isup * 8192;
#pragma unroll
        for (int ks = 0; ks < 4; ks++) {
            int kb = ks * 32;
            uint32_t ah[2][4], al[2][4];
#pragma unroll
            for (int mt = 0; mt < 2; mt++) {
                int row = wm * 32 + mt * 16 + (lid & 15);
                uint32_t bo = (uint32_t)(row * 128 + kb + ((lid >> 4) << 4));
                uint32_t ad = sA + (bo ^ ((row & 7) << 4));
                ldsm4(ah[mt], ad);
                ldsm4(al[mt], ad + 16384);
            }
#pragma unroll
            for (int ng = 0; ng < 4; ng++) {
                int nrow = ng * 16 + (lid & 7) + ((lid >> 4) << 3);
                uint32_t bo = (uint32_t)(nrow * 128 + kb + (((lid >> 3) & 1) << 4));
                uint32_t ad = sBb + (bo ^ ((nrow & 7) << 4));
                uint32_t bh[4];
                ldsm4(bh, ad);
#pragma unroll
                for (int mt = 0; mt < 2; mt++)
#pragma unroll
                    for (int p = 0; p < 2; p++) {
                        int nt = ng * 2 + p;
                        mma16816(acc[mt][nt], ah[mt], bh + 2 * p);
                        mma16816(acc[mt][nt], al[mt], bh + 2 * p);
                    }
            }
        }
        __syncthreads();          // all warps done before next overwrite
    }

    // epilogue: up warps stash U to smem; gate warps combine silu(g)*u
    float* u_s = (float*)smem;                     // [128][66]
    __half* h_s = (__half*)(smem + 34816);         // [128][72]
    __half* l_s = (__half*)(smem + 53248);         // [128][72]
    if (isup) {
#pragma unroll
        for (int mt = 0; mt < 2; mt++)
#pragma unroll
            for (int nt = 0; nt < 8; nt++) {
                int r_ = wm * 32 + mt * 16 + (lid >> 2);
                int c_ = nt * 8 + 2 * (lid & 3);
                *(float2*)&u_s[r_ * 66 + c_]       = make_float2(acc[mt][nt][0], acc[mt][nt][1]);
                *(float2*)&u_s[(r_ + 8) * 66 + c_] = make_float2(acc[mt][nt][2], acc[mt][nt][3]);
            }
    }
    __syncthreads();
    if (!isup) {
#pragma unroll
        for (int mt = 0; mt < 2; mt++)
#pragma unroll
            for (int nt = 0; nt < 8; nt++) {
                int r_ = wm * 32 + mt * 16 + (lid >> 2);
                int c_ = nt * 8 + 2 * (lid & 3);
#pragma unroll
                for (int hh = 0; hh < 2; hh++) {
                    int rr = r_ + hh * 8;
                    float2 u = *(float2*)&u_s[rr * 66 + c_];
                    float o0 = silu(acc[mt][nt][2 * hh + 0]) * u.x;
                    float o1 = silu(acc[mt][nt][2 * hh + 1]) * u.y;
                    __half h0 = __float2half_rn(o0), h1 = __float2half_rn(o1);
                    __half q0 = __float2half_rn(o0 - __half2float(h0));
                    __half q1 = __float2half_rn(o1 - __half2float(h1));
                    __half2 hp{h0, h1}, lp{q0, q1};
                    *(uint32_t*)&h_s[rr * 72 + c_] = *(uint32_t*)&hp;
                    *(uint32_t*)&l_s[rr * 72 + c_] = *(uint32_t*)&lp;
                }
            }
    }
    __syncthreads();
    __half* AH = ROUTED ? g_arth : g_acth;
    __half* AL = ROUTED ? g_artl : g_actl;
    for (int i = tid; i < 128 * 8; i += 256) {
        int row = i >> 3, vv = i & 7;
        if (ROUTED && r0 + row >= r1) continue;
        *(uint4*)(AH + (size_t)(r0 + row) * NI + n0 + vv * 8) = *(uint4*)(h_s + row * 72 + vv * 8);
        *(uint4*)(AL + (size_t)(r0 + row) * NI + n0 + vv * 8) = *(uint4*)(l_s + row * 72 + vv * 8);
    }
}

// ---------------- Down-proj HMMA GEMM (fp16 2-pass, single-buffer, occ 2) ---
// Block: 128 rows x 128 cols, K-stage 64. Stage (48KB): Ah 16K | Al 16K | B 16K.
#define DN_SMEM 67584
template <bool ROUTED>
__global__ __launch_bounds__(256, 2) void k_down_mma(float* __restrict__ OUT) {
    extern __shared__ char smem[];
    const int KI = ROUTED ? IEXP : ISH;
    const __half* AHs = ROUTED ? g_arth : g_acth;
    const __half* ALs = ROUTED ? g_artl : g_actl;
    int r0, r1;
    const __half* W;
    if (ROUTED) {
        int e = blockIdx.x >> 5, mt = blockIdx.x & 31;
        r0 = g_off[e] + mt * 128;
        int re = g_off[e + 1];
        if (r0 >= re) return;
        r1 = min(re, r0 + 128);
        W = g_w2h + (size_t)e * DMODEL * IEXP;
    } else {
        r0 = blockIdx.x * 128; r1 = r0 + 128;
        W = g_w2sh;
    }
    const int n0  = blockIdx.y * 128;
    const int tid = threadIdx.x, wid = tid >> 5, lid = tid & 31;
    const int wm = wid & 3, wn = wid >> 2;
    uint32_t sb = smem_u32(smem);

    const int lrow = tid >> 3, v = tid & 7;
    uint32_t so[4], aof[4], bof[4];
#pragma unroll
    for (int j = 0; j < 4; j++) {
        int rr = lrow + 32 * j;
        so[j]  = swz((uint32_t)(rr * 128 + v * 16));
        aof[j] = (uint32_t)(min(r0 + rr, r1 - 1) * KI + v * 8);
        bof[j] = (uint32_t)((n0 + rr) * KI + v * 8);
    }

    float acc[2][8][4];
#pragma unroll
    for (int a = 0; a < 2; a++)
#pragma unroll
        for (int b = 0; b < 8; b++)
#pragma unroll
            for (int c = 0; c < 4; c++) acc[a][b][c] = 0.0f;

    const int S = KI / 64;
    for (int s = 0; s < S; s++) {
        int kof = s * 64;
#pragma unroll
        for (int j = 0; j < 4; j++) {
            cpa16(sb +     0 + so[j], AHs + aof[j] + kof);
            cpa16(sb + 16384 + so[j], ALs + aof[j] + kof);
            cpa16(sb + 32768 + so[j], W + bof[j] + kof);
        }
        cpa_commit();
        cpa_wait<0>();
        __syncthreads();
        uint32_t sA = sb, sBb = sb + 32768;
#pragma unroll
        for (int ks = 0; ks < 4; ks++) {
            int kb = ks * 32;
            uint32_t ah[2][4], al[2][4];
#pragma unroll
            for (int mt = 0; mt < 2; mt++) {
                int row = wm * 32 + mt * 16 + (lid & 15);
                uint32_t bo = (uint32_t)(row * 128 + kb + ((lid >> 4) << 4));
                uint32_t ad = sA + (bo ^ ((row & 7) << 4));
                ldsm4(ah[mt], ad);
                ldsm4(al[mt], ad + 16384);
            }
#pragma unroll
            for (int ng = 0; ng < 4; ng++) {
                int nrow = wn * 64 + ng * 16 + (lid & 7) + ((lid >> 4) << 3);
                uint32_t bo = (uint32_t)(nrow * 128 + kb + (((lid >> 3) & 1) << 4));
                uint32_t ad = sBb + (bo ^ ((nrow & 7) << 4));
                uint32_t bh[4];
                ldsm4(bh, ad);
#pragma unroll
                for (int mt = 0; mt < 2; mt++)
#pragma unroll
                    for (int p = 0; p < 2; p++) {
                        int nt = ng * 2 + p;
                        mma16816(acc[mt][nt], ah[mt], bh + 2 * p);
                        mma16816(acc[mt][nt], al[mt], bh + 2 * p);
                    }
            }
        }
        __syncthreads();
    }

    // epilogue via smem f32 tile [128][132]
    float* c_s = (float*)smem;
#pragma unroll
    for (int mt = 0; mt < 2; mt++)
#pragma unroll
        for (int nt = 0; nt < 8; nt++) {
            int r_ = wm * 32 + mt * 16 + (lid >> 2);
            int c_ = wn * 64 + nt * 8 + 2 * (lid & 3);
            *(float2*)&c_s[r_ * 132 + c_]       = make_float2(acc[mt][nt][0], acc[mt][nt][1]);
            *(float2*)&c_s[(r_ + 8) * 132 + c_] = make_float2(acc[mt][nt][2], acc[mt][nt][3]);
        }
    __syncthreads();
    if (!ROUTED) {
        for (int i = tid; i < 128 * 32; i += 256) {
            int row = i >> 5, vv = i & 31;
            *(float4*)(OUT + (size_t)(r0 + row) * DMODEL + n0 + vv * 4) =
                *(float4*)(c_s + row * 132 + vv * 4);
        }
    } else {
        for (int i = tid; i < 128 * 32; i += 256) {
            int row = i >> 5, vv = i & 31;
            if (r0 + row < r1)
                *(float4*)(g_dnout + (size_t)(r0 + row) * DMODEL + n0 + vv * 4) =
                    *(float4*)(c_s + row * 132 + vv * 4);
        }
    }
}

// ---------------- launch ---------------------------------------------------
extern "C" void kernel_launch(void* const* d_in, const int* in_sizes, int n_in,
                              void* d_out, int out_size) {
    const float* x      = (const float*)d_in[0];
    const float* logits = (const float*)d_in[1];
    const float* w13    = (const float*)d_in[2];
    const float* w2     = (const float*)d_in[3];
    const float* w13s   = (const float*)d_in[4];
    const float* w2s    = (const float*)d_in[5];
    float* out = (float*)d_out;
    float* shared_out = out;
    float* fused_out  = out + (size_t)T_TOK * DMODEL;

    static cudaStream_t sB = nullptr;
    static cudaEvent_t evX = nullptr, evJoin = nullptr;
    if (!sB) {
        cudaStreamCreateWithFlags(&sB, cudaStreamNonBlocking);
        cudaEventCreateWithFlags(&evX, cudaEventDisableTiming);
        cudaEventCreateWithFlags(&evJoin, cudaEventDisableTiming);
        cudaFuncSetAttribute(k_swiglu_mma<false>, cudaFuncAttributeMaxDynamicSharedMemorySize, SW_SMEM);
        cudaFuncSetAttribute(k_swiglu_mma<true>,  cudaFuncAttributeMaxDynamicSharedMemorySize, SW_SMEM);
        cudaFuncSetAttribute(k_down_mma<false>,   cudaFuncAttributeMaxDynamicSharedMemorySize, DN_SMEM);
        cudaFuncSetAttribute(k_down_mma<true>,    cudaFuncAttributeMaxDynamicSharedMemorySize, DN_SMEM);
    }

    __half *xh, *xl, *w13h, *w2h, *w13sh, *w2sh;
    cudaGetSymbolAddress((void**)&xh, g_xh);     cudaGetSymbolAddress((void**)&xl, g_xl);
    cudaGetSymbolAddress((void**)&w13h, g_w13h); cudaGetSymbolAddress((void**)&w2h, g_w2h);
    cudaGetSymbolAddress((void**)&w13sh, g_w13sh);
    cudaGetSymbolAddress((void**)&w2sh, g_w2sh);

    auto cvtHL = [](cudaStream_t st, const float* src, __half* h, __half* l, int n) {
        int n4 = n / 4;
        k_cvtHL<<<(n4 + 255) / 256, 256, 0, st>>>((const float4*)src, (uint2*)h, (uint2*)l, n4);
    };
    auto cvtH = [](cudaStream_t st, const float* src, __half* h, int n) {
        int n4 = n / 4;
        k_cvtH<<<(n4 + 255) / 256, 256, 0, st>>>((const float4*)src, (uint2*)h, n4);
    };

    // ---- stream A: shared-expert path -------------------------------------
    cvtHL(0, x, xh, xl, T_TOK * DMODEL);            // launch 0
    cudaEventRecord(evX, 0);                        // fork: B only needs x
    cvtH(0, w13s, w13sh, 2 * ISH * DMODEL);         // launch 1
    cvtH(0, w2s,  w2sh,  DMODEL * ISH);             // launch 2
    {
        dim3 g(T_TOK / 128, ISH / 64);              // launch 3 — ncu target
        k_swiglu_mma<false><<<g, 256, SW_SMEM>>>();
    }

    // ---- stream B: routing + routed path (overlaps swiglu_sh) -------------
    cudaStreamWaitEvent(sB, evX, 0);
    k_init<<<1, 32, 0, sB>>>();
    k_router<<<(T_TOK + 255) / 256, 256, 0, sB>>>(logits);
    k_prefix<<<1, 32, 0, sB>>>();
    k_scatter<<<(T_TOK + 255) / 256, 256, 0, sB>>>();
    cvtH(sB, w13, w13h, NEXP * 2 * IEXP * DMODEL);
    cvtH(sB, w2,  w2h,  NEXP * DMODEL * IEXP);
    {
        dim3 g(NEXP * 32, IEXP / 64);
        k_swiglu_mma<true><<<g, 256, SW_SMEM, sB>>>();
    }
    {
        dim3 g(NEXP * 32, DMODEL / 128);
        k_down_mma<true><<<g, 256, DN_SMEM, sB>>>(nullptr);
    }
    k_combine<<<(T_TOK * DMODEL / 4 + 255) / 256, 256, 0, sB>>>(fused_out);
    cudaEventRecord(evJoin, sB);

    // ---- stream A continues: shared down-proj ------------------------------
    {
        dim3 g(T_TOK / 128, DMODEL / 128);
        k_down_mma<false><<<g, 256, DN_SMEM>>>(shared_out);
    }
    cudaStreamWaitEvent(0, evJoin, 0);
}

// round 17
// speedup vs baseline: 1.4450x; 1.0082x over previous
#include <cuda_runtime.h>
#include <cuda_fp16.h>
#include <cstdint>

// Fixed problem shapes
#define T_TOK  4096
#define DMODEL 1024
#define NEXP   16
#define IEXP   512
#define ISH    2048
#define MAXROWS (2 * T_TOK)

typedef unsigned long long u64;

// ---------------- scratch (device globals; no allocation allowed) ----------
static __device__ int   g_cnt[NEXP];
static __device__ int   g_off[NEXP + 1];
static __device__ int   g_cur[NEXP];
static __device__ int   g_rows[MAXROWS];
static __device__ int   g_slot[T_TOK * 2];
static __device__ int   g_eidx[T_TOK * 2];
static __device__ float g_twt[T_TOK * 2];

// fp16 operands: x/activations split hi+lo; weights truncated hi-only
static __device__ __half g_xh[(size_t)T_TOK * DMODEL];
static __device__ __half g_xl[(size_t)T_TOK * DMODEL];
static __device__ __half g_w13h[(size_t)NEXP * 2 * IEXP * DMODEL];
static __device__ __half g_w2h[(size_t)NEXP * DMODEL * IEXP];
static __device__ __half g_w13sh[(size_t)2 * ISH * DMODEL];
static __device__ __half g_w2sh[(size_t)DMODEL * ISH];
// activations (hi/lo)
static __device__ __half g_acth[(size_t)T_TOK * ISH];
static __device__ __half g_actl[(size_t)T_TOK * ISH];
static __device__ __half g_arth[(size_t)MAXROWS * IEXP];
static __device__ __half g_artl[(size_t)MAXROWS * IEXP];
// routed down-proj output, packed rows (combined later; no atomics)
static __device__ float g_dnout[(size_t)MAXROWS * DMODEL];

// ---------------- PTX helpers ----------------------------------------------
__device__ __forceinline__ uint32_t smem_u32(const void* p) {
    uint32_t a;
    asm("{ .reg .u64 t; cvta.to.shared.u64 t, %1; cvt.u32.u64 %0, t; }" : "=r"(a) : "l"(p));
    return a;
}
__device__ __forceinline__ void cpa16(uint32_t s, const void* g) {
    asm volatile("cp.async.cg.shared.global [%0], [%1], 16;" :: "r"(s), "l"(g) : "memory");
}
__device__ __forceinline__ void cpa_commit() {
    asm volatile("cp.async.commit_group;" ::: "memory");
}
template <int N>
__device__ __forceinline__ void cpa_wait() {
    asm volatile("cp.async.wait_group %0;" :: "n"(N) : "memory");
}
__device__ __forceinline__ void ldsm4(uint32_t* r, uint32_t addr) {
    asm volatile("ldmatrix.sync.aligned.m8n8.x4.shared.b16 {%0,%1,%2,%3}, [%4];"
        : "=r"(r[0]), "=r"(r[1]), "=r"(r[2]), "=r"(r[3]) : "r"(addr));
}
// fp16 MMA, fp32 accumulate
__device__ __forceinline__ void mma16816(float* d, const uint32_t* a, const uint32_t* b) {
    asm volatile(
        "mma.sync.aligned.m16n8k16.row.col.f32.f16.f16.f32 "
        "{%0,%1,%2,%3}, {%4,%5,%6,%7}, {%8,%9}, {%0,%1,%2,%3};"
        : "+f"(d[0]), "+f"(d[1]), "+f"(d[2]), "+f"(d[3])
        : "r"(a[0]), "r"(a[1]), "r"(a[2]), "r"(a[3]), "r"(b[0]), "r"(b[1]));
}
__device__ __forceinline__ uint32_t swz(uint32_t bo) { return bo ^ ((bo >> 3) & 0x70); }
__device__ __forceinline__ float silu(float x) { return x / (1.0f + __expf(-x)); }

// ---------------- small kernels -------------------------------------------
__global__ void k_init() {
    if (threadIdx.x < NEXP) g_cnt[threadIdx.x] = 0;
}

__global__ void k_router(const float* __restrict__ logits) {
    int t = blockIdx.x * blockDim.x + threadIdx.x;
    if (t >= T_TOK) return;
    const float* l = logits + (size_t)t * NEXP;
    float m1 = -3.4e38f, m2 = -3.4e38f;
    int i1 = 0, i2 = 0;
#pragma unroll
    for (int e = 0; e < NEXP; e++) {
        float v = l[e];
        if (v > m1) { m2 = m1; i2 = i1; m1 = v; i1 = e; }
        else if (v > m2) { m2 = v; i2 = e; }
    }
    float r   = expf(m2 - m1);
    float w2v = r / (1.0f + r);
    float w1v = 1.0f - w2v;
    g_eidx[t * 2 + 0] = i1; g_eidx[t * 2 + 1] = i2;
    g_twt [t * 2 + 0] = w1v; g_twt[t * 2 + 1] = w2v;
    atomicAdd(&g_cnt[i1], 1);
    atomicAdd(&g_cnt[i2], 1);
}

__global__ void k_prefix() {
    if (threadIdx.x == 0) {
        int s = 0;
        for (int e = 0; e < NEXP; e++) { g_off[e] = s; g_cur[e] = s; s += g_cnt[e]; }
        g_off[NEXP] = s;
    }
}

__global__ void k_scatter() {
    int t = blockIdx.x * blockDim.x + threadIdx.x;
    if (t >= T_TOK) return;
#pragma unroll
    for (int k = 0; k < 2; k++) {
        int e = g_eidx[t * 2 + k];
        int pos = atomicAdd(&g_cur[e], 1);
        g_rows[pos] = t;
        g_slot[t * 2 + k] = pos;
    }
}

// fp32 -> fp16 hi/lo split (for x)
__global__ void k_cvtHL(const float4* __restrict__ s, uint2* __restrict__ h,
                        uint2* __restrict__ l, int n4) {
    int i = blockIdx.x * blockDim.x + threadIdx.x;
    if (i >= n4) return;
    float4 v = s[i];
    __half h0 = __float2half_rn(v.x), h1 = __float2half_rn(v.y);
    __half h2 = __float2half_rn(v.z), h3 = __float2half_rn(v.w);
    __half l0 = __float2half_rn(v.x - __half2float(h0));
    __half l1 = __float2half_rn(v.y - __half2float(h1));
    __half l2 = __float2half_rn(v.z - __half2float(h2));
    __half l3 = __float2half_rn(v.w - __half2float(h3));
    __half2 hp0{h0, h1}, hp1{h2, h3}, lp0{l0, l1}, lp1{l2, l3};
    uint2 hh, ll;
    hh.x = *(uint32_t*)&hp0; hh.y = *(uint32_t*)&hp1;
    ll.x = *(uint32_t*)&lp0; ll.y = *(uint32_t*)&lp1;
    h[i] = hh; l[i] = ll;
}

// fp32 -> fp16 truncate-only (for weights)
__global__ void k_cvtH(const float4* __restrict__ s, uint2* __restrict__ h, int n4) {
    int i = blockIdx.x * blockDim.x + threadIdx.x;
    if (i >= n4) return;
    float4 v = s[i];
    __half2 hp0{__float2half_rn(v.x), __float2half_rn(v.y)};
    __half2 hp1{__float2half_rn(v.z), __float2half_rn(v.w)};
    uint2 hh;
    hh.x = *(uint32_t*)&hp0; hh.y = *(uint32_t*)&hp1;
    h[i] = hh;
}

// combine: fused_out[t] = w0 * dnout[slot0(t)] + w1 * dnout[slot1(t)]
__global__ void k_combine(float* __restrict__ fo) {
    int i = blockIdx.x * blockDim.x + threadIdx.x;
    if (i >= T_TOK * DMODEL / 4) return;
    int t = i / (DMODEL / 4);
    int c = (i % (DMODEL / 4)) * 4;
    float w0 = g_twt[2 * t], w1 = g_twt[2 * t + 1];
    const float4 a = *(const float4*)&g_dnout[(size_t)g_slot[2 * t]     * DMODEL + c];
    const float4 b = *(const float4*)&g_dnout[(size_t)g_slot[2 * t + 1] * DMODEL + c];
    float4 r;
    r.x = w0 * a.x + w1 * b.x;
    r.y = w0 * a.y + w1 * b.y;
    r.z = w0 * a.z + w1 * b.z;
    r.w = w0 * a.w + w1 * b.w;
    *(float4*)&fo[(size_t)t * DMODEL + c] = r;
}

// ---------------- SwiGLU HMMA GEMM (fp16 2-pass, K64 double-buffer, occ 2) --
// Block: 128 token rows x 64 gate + 64 up cols. K-stage 64, ping-pong.
// Stage (48KB): Ah 16K | Al 16K | G 8K | U 8K. 2 passes: Ah*B + Al*B.
#define SW_STG  49152
#define SW_SMEM (2 * SW_STG)   // 96 KB; 2 CTAs = 192 KB <= 227 KB
template <bool ROUTED>
__global__ __launch_bounds__(256, 2) void k_swiglu_mma() {
    extern __shared__ char smem[];
    const int NI = ROUTED ? IEXP : ISH;
    int r0, r1;
    const __half* W;
    if (ROUTED) {
        int e = blockIdx.x >> 5, mt = blockIdx.x & 31;
        r0 = g_off[e] + mt * 128;
        int re = g_off[e + 1];
        if (r0 >= re) return;
        r1 = min(re, r0 + 128);
        W = g_w13h + (size_t)e * 2 * IEXP * DMODEL;
    } else {
        r0 = blockIdx.x * 128; r1 = r0 + 128;
        W = g_w13sh;
    }
    const int n0  = blockIdx.y * 64;
    const int tid = threadIdx.x, wid = tid >> 5, lid = tid & 31;
    const int wm = wid & 3, isup = wid >> 2;
    uint32_t sb = smem_u32(smem);
    const __half *Xh = g_xh, *Xl = g_xl;

    // loader precompute: 128-byte rows (64 f16)
    const int lrow = tid >> 3, v = tid & 7;
    uint32_t soA[4], aof[4];
#pragma unroll
    for (int j = 0; j < 4; j++) {
        int rr = lrow + 32 * j;
        soA[j] = swz((uint32_t)(rr * 128 + v * 16));
        int ar = r0 + rr;
        if (ROUTED) ar = g_rows[min(ar, r1 - 1)];
        aof[j] = (uint32_t)(ar * DMODEL + v * 8);
    }
    uint32_t soB[2], gof[2], uof[2];
#pragma unroll
    for (int j = 0; j < 2; j++) {
        int rr = lrow + 32 * j;
        soB[j] = swz((uint32_t)(rr * 128 + v * 16));
        gof[j] = (uint32_t)((n0 + rr) * DMODEL + v * 8);
        uof[j] = (uint32_t)((NI + n0 + rr) * DMODEL + v * 8);
    }

    float acc[2][8][4];
#pragma unroll
    for (int a = 0; a < 2; a++)
#pragma unroll
        for (int b = 0; b < 8; b++)
#pragma unroll
            for (int c = 0; c < 4; c++) acc[a][b][c] = 0.0f;

    const int S = DMODEL / 64;   // 16

#define SW_ISSUE(stg)                                                          \
    {                                                                          \
        uint32_t tb = sb + ((stg) & 1) * SW_STG;                               \
        int kof = (stg) * 64;                                                  \
        _Pragma("unroll")                                                      \
        for (int j = 0; j < 4; j++) {                                          \
            cpa16(tb +     0 + soA[j], Xh + aof[j] + kof);                     \
            cpa16(tb + 16384 + soA[j], Xl + aof[j] + kof);                     \
        }                                                                      \
        _Pragma("unroll")                                                      \
        for (int j = 0; j < 2; j++) {                                          \
            cpa16(tb + 32768 + soB[j], W + gof[j] + kof);                      \
            cpa16(tb + 40960 + soB[j], W + uof[j] + kof);                      \
        }                                                                      \
        cpa_commit();                                                          \
    }

    SW_ISSUE(0);
    for (int s = 0; s < S; s++) {
        if (s + 1 < S) { SW_ISSUE(s + 1); cpa_wait<1>(); }
        else            cpa_wait<0>();
        __syncthreads();
        uint32_t tb = sb + (s & 1) * SW_STG;
        uint32_t sA = tb;
        uint32_t sBb = tb + 32768 + isup * 8192;
#pragma unroll
        for (int ks = 0; ks < 4; ks++) {
            int kb = ks * 32;
            uint32_t ah[2][4], al[2][4];
#pragma unroll
            for (int mt = 0; mt < 2; mt++) {
                int row = wm * 32 + mt * 16 + (lid & 15);
                uint32_t bo = (uint32_t)(row * 128 + kb + ((lid >> 4) << 4));
                uint32_t ad = sA + (bo ^ ((row & 7) << 4));
                ldsm4(ah[mt], ad);
                ldsm4(al[mt], ad + 16384);
            }
#pragma unroll
            for (int ng = 0; ng < 4; ng++) {
                int nrow = ng * 16 + (lid & 7) + ((lid >> 4) << 3);
                uint32_t bo = (uint32_t)(nrow * 128 + kb + (((lid >> 3) & 1) << 4));
                uint32_t ad = sBb + (bo ^ ((nrow & 7) << 4));
                uint32_t bh[4];
                ldsm4(bh, ad);
#pragma unroll
                for (int mt = 0; mt < 2; mt++)
#pragma unroll
                    for (int p = 0; p < 2; p++) {
                        int nt = ng * 2 + p;
                        mma16816(acc[mt][nt], ah[mt], bh + 2 * p);
                        mma16816(acc[mt][nt], al[mt], bh + 2 * p);
                    }
            }
        }
        __syncthreads();
    }
#undef SW_ISSUE

    // epilogue: up warps stash U to smem; gate warps combine silu(g)*u
    float* u_s = (float*)smem;                     // [128][66]
    __half* h_s = (__half*)(smem + 34816);         // [128][72]
    __half* l_s = (__half*)(smem + 53248);         // [128][72]
    if (isup) {
#pragma unroll
        for (int mt = 0; mt < 2; mt++)
#pragma unroll
            for (int nt = 0; nt < 8; nt++) {
                int r_ = wm * 32 + mt * 16 + (lid >> 2);
                int c_ = nt * 8 + 2 * (lid & 3);
                *(float2*)&u_s[r_ * 66 + c_]       = make_float2(acc[mt][nt][0], acc[mt][nt][1]);
                *(float2*)&u_s[(r_ + 8) * 66 + c_] = make_float2(acc[mt][nt][2], acc[mt][nt][3]);
            }
    }
    __syncthreads();
    if (!isup) {
#pragma unroll
        for (int mt = 0; mt < 2; mt++)
#pragma unroll
            for (int nt = 0; nt < 8; nt++) {
                int r_ = wm * 32 + mt * 16 + (lid >> 2);
                int c_ = nt * 8 + 2 * (lid & 3);
#pragma unroll
                for (int hh = 0; hh < 2; hh++) {
                    int rr = r_ + hh * 8;
                    float2 u = *(float2*)&u_s[rr * 66 + c_];
                    float o0 = silu(acc[mt][nt][2 * hh + 0]) * u.x;
                    float o1 = silu(acc[mt][nt][2 * hh + 1]) * u.y;
                    __half h0 = __float2half_rn(o0), h1 = __float2half_rn(o1);
                    __half q0 = __float2half_rn(o0 - __half2float(h0));
                    __half q1 = __float2half_rn(o1 - __half2float(h1));
                    __half2 hp{h0, h1}, lp{q0, q1};
                    *(uint32_t*)&h_s[rr * 72 + c_] = *(uint32_t*)&hp;
                    *(uint32_t*)&l_s[rr * 72 + c_] = *(uint32_t*)&lp;
                }
            }
    }
    __syncthreads();
    __half* AH = ROUTED ? g_arth : g_acth;
    __half* AL = ROUTED ? g_artl : g_actl;
    for (int i = tid; i < 128 * 8; i += 256) {
        int row = i >> 3, vv = i & 7;
        if (ROUTED && r0 + row >= r1) continue;
        *(uint4*)(AH + (size_t)(r0 + row) * NI + n0 + vv * 8) = *(uint4*)(h_s + row * 72 + vv * 8);
        *(uint4*)(AL + (size_t)(r0 + row) * NI + n0 + vv * 8) = *(uint4*)(l_s + row * 72 + vv * 8);
    }
}

// ---------------- Down-proj HMMA GEMM (fp16 2-pass, K64 double-buffer, occ 2)
// Block: 128 rows x 128 cols, K-stage 64. Stage (48KB): Ah 16K | Al 16K | B 16K.
#define DN_STG  49152
#define DN_SMEM (2 * DN_STG)   // 96 KB; epilogue 67.6K fits
template <bool ROUTED>
__global__ __launch_bounds__(256, 2) void k_down_mma(float* __restrict__ OUT) {
    extern __shared__ char smem[];
    const int KI = ROUTED ? IEXP : ISH;
    const __half* AHs = ROUTED ? g_arth : g_acth;
    const __half* ALs = ROUTED ? g_artl : g_actl;
    int r0, r1;
    const __half* W;
    if (ROUTED) {
        int e = blockIdx.x >> 5, mt = blockIdx.x & 31;
        r0 = g_off[e] + mt * 128;
        int re = g_off[e + 1];
        if (r0 >= re) return;
        r1 = min(re, r0 + 128);
        W = g_w2h + (size_t)e * DMODEL * IEXP;
    } else {
        r0 = blockIdx.x * 128; r1 = r0 + 128;
        W = g_w2sh;
    }
    const int n0  = blockIdx.y * 128;
    const int tid = threadIdx.x, wid = tid >> 5, lid = tid & 31;
    const int wm = wid & 3, wn = wid >> 2;
    uint32_t sb = smem_u32(smem);

    const int lrow = tid >> 3, v = tid & 7;
    uint32_t so[4], aof[4], bof[4];
#pragma unroll
    for (int j = 0; j < 4; j++) {
        int rr = lrow + 32 * j;
        so[j]  = swz((uint32_t)(rr * 128 + v * 16));
        aof[j] = (uint32_t)(min(r0 + rr, r1 - 1) * KI + v * 8);
        bof[j] = (uint32_t)((n0 + rr) * KI + v * 8);
    }

    float acc[2][8][4];
#pragma unroll
    for (int a = 0; a < 2; a++)
#pragma unroll
        for (int b = 0; b < 8; b++)
#pragma unroll
            for (int c = 0; c < 4; c++) acc[a][b][c] = 0.0f;

    const int S = KI / 64;

#define DN_ISSUE(stg)                                                          \
    {                                                                          \
        uint32_t tb = sb + ((stg) & 1) * DN_STG;                               \
        int kof = (stg) * 64;                                                  \
        _Pragma("unroll")                                                      \
        for (int j = 0; j < 4; j++) {                                          \
            cpa16(tb +     0 + so[j], AHs + aof[j] + kof);                     \
            cpa16(tb + 16384 + so[j], ALs + aof[j] + kof);                     \
            cpa16(tb + 32768 + so[j], W + bof[j] + kof);                       \
        }                                                                      \
        cpa_commit();                                                          \
    }

    DN_ISSUE(0);
    for (int s = 0; s < S; s++) {
        if (s + 1 < S) { DN_ISSUE(s + 1); cpa_wait<1>(); }
        else            cpa_wait<0>();
        __syncthreads();
        uint32_t tb = sb + (s & 1) * DN_STG;
        uint32_t sA = tb, sBb = tb + 32768;
#pragma unroll
        for (int ks = 0; ks < 4; ks++) {
            int kb = ks * 32;
            uint32_t ah[2][4], al[2][4];
#pragma unroll
            for (int mt = 0; mt < 2; mt++) {
                int row = wm * 32 + mt * 16 + (lid & 15);
                uint32_t bo = (uint32_t)(row * 128 + kb + ((lid >> 4) << 4));
                uint32_t ad = sA + (bo ^ ((row & 7) << 4));
                ldsm4(ah[mt], ad);
                ldsm4(al[mt], ad + 16384);
            }
#pragma unroll
            for (int ng = 0; ng < 4; ng++) {
                int nrow = wn * 64 + ng * 16 + (lid & 7) + ((lid >> 4) << 3);
                uint32_t bo = (uint32_t)(nrow * 128 + kb + (((lid >> 3) & 1) << 4));
                uint32_t ad = sBb + (bo ^ ((nrow & 7) << 4));
                uint32_t bh[4];
                ldsm4(bh, ad);
#pragma unroll
                for (int mt = 0; mt < 2; mt++)
#pragma unroll
                    for (int p = 0; p < 2; p++) {
                        int nt = ng * 2 + p;
                        mma16816(acc[mt][nt], ah[mt], bh + 2 * p);
                        mma16816(acc[mt][nt], al[mt], bh + 2 * p);
                    }
            }
        }
        __syncthreads();
    }
#undef DN_ISSUE

    // epilogue via smem f32 tile [128][132]
    float* c_s = (float*)smem;
#pragma unroll
    for (int mt = 0; mt < 2; mt++)
#pragma unroll
        for (int nt = 0; nt < 8; nt++) {
            int r_ = wm * 32 + mt * 16 + (lid >> 2);
            int c_ = wn * 64 + nt * 8 + 2 * (lid & 3);
            *(float2*)&c_s[r_ * 132 + c_]       = make_float2(acc[mt][nt][0], acc[mt][nt][1]);
            *(float2*)&c_s[(r_ + 8) * 132 + c_] = make_float2(acc[mt][nt][2], acc[mt][nt][3]);
        }
    __syncthreads();
    if (!ROUTED) {
        for (int i = tid; i < 128 * 32; i += 256) {
            int row = i >> 5, vv = i & 31;
            *(float4*)(OUT + (size_t)(r0 + row) * DMODEL + n0 + vv * 4) =
                *(float4*)(c_s + row * 132 + vv * 4);
        }
    } else {
        for (int i = tid; i < 128 * 32; i += 256) {
            int row = i >> 5, vv = i & 31;
            if (r0 + row < r1)
                *(float4*)(g_dnout + (size_t)(r0 + row) * DMODEL + n0 + vv * 4) =
                    *(float4*)(c_s + row * 132 + vv * 4);
        }
    }
}

// ---------------- launch ---------------------------------------------------
extern "C" void kernel_launch(void* const* d_in, const int* in_sizes, int n_in,
                              void* d_out, int out_size) {
    const float* x      = (const float*)d_in[0];
    const float* logits = (const float*)d_in[1];
    const float* w13    = (const float*)d_in[2];
    const float* w2     = (const float*)d_in[3];
    const float* w13s   = (const float*)d_in[4];
    const float* w2s    = (const float*)d_in[5];
    float* out = (float*)d_out;
    float* shared_out = out;
    float* fused_out  = out + (size_t)T_TOK * DMODEL;

    static cudaStream_t sB = nullptr;
    static cudaEvent_t evX = nullptr, evJoin = nullptr;
    if (!sB) {
        cudaStreamCreateWithFlags(&sB, cudaStreamNonBlocking);
        cudaEventCreateWithFlags(&evX, cudaEventDisableTiming);
        cudaEventCreateWithFlags(&evJoin, cudaEventDisableTiming);
        cudaFuncSetAttribute(k_swiglu_mma<false>, cudaFuncAttributeMaxDynamicSharedMemorySize, SW_SMEM);
        cudaFuncSetAttribute(k_swiglu_mma<true>,  cudaFuncAttributeMaxDynamicSharedMemorySize, SW_SMEM);
        cudaFuncSetAttribute(k_down_mma<false>,   cudaFuncAttributeMaxDynamicSharedMemorySize, DN_SMEM);
        cudaFuncSetAttribute(k_down_mma<true>,    cudaFuncAttributeMaxDynamicSharedMemorySize, DN_SMEM);
    }

    __half *xh, *xl, *w13h, *w2h, *w13sh, *w2sh;
    cudaGetSymbolAddress((void**)&xh, g_xh);     cudaGetSymbolAddress((void**)&xl, g_xl);
    cudaGetSymbolAddress((void**)&w13h, g_w13h); cudaGetSymbolAddress((void**)&w2h, g_w2h);
    cudaGetSymbolAddress((void**)&w13sh, g_w13sh);
    cudaGetSymbolAddress((void**)&w2sh, g_w2sh);

    auto cvtHL = [](cudaStream_t st, const float* src, __half* h, __half* l, int n) {
        int n4 = n / 4;
        k_cvtHL<<<(n4 + 255) / 256, 256, 0, st>>>((const float4*)src, (uint2*)h, (uint2*)l, n4);
    };
    auto cvtH = [](cudaStream_t st, const float* src, __half* h, int n) {
        int n4 = n / 4;
        k_cvtH<<<(n4 + 255) / 256, 256, 0, st>>>((const float4*)src, (uint2*)h, n4);
    };

    // ---- stream A: shared-expert path -------------------------------------
    cvtHL(0, x, xh, xl, T_TOK * DMODEL);            // launch 0
    cudaEventRecord(evX, 0);                        // fork: B only needs x
    cvtH(0, w13s, w13sh, 2 * ISH * DMODEL);         // launch 1
    cvtH(0, w2s,  w2sh,  DMODEL * ISH);             // launch 2
    {
        dim3 g(T_TOK / 128, ISH / 64);              // launch 3 — ncu target
        k_swiglu_mma<false><<<g, 256, SW_SMEM>>>();
    }

    // ---- stream B: routing + routed path (overlaps swiglu_sh) -------------
    cudaStreamWaitEvent(sB, evX, 0);
    k_init<<<1, 32, 0, sB>>>();
    k_router<<<(T_TOK + 255) / 256, 256, 0, sB>>>(logits);
    k_prefix<<<1, 32, 0, sB>>>();
    k_scatter<<<(T_TOK + 255) / 256, 256, 0, sB>>>();
    cvtH(sB, w13, w13h, NEXP * 2 * IEXP * DMODEL);
    cvtH(sB, w2,  w2h,  NEXP * DMODEL * IEXP);
    {
        dim3 g(NEXP * 32, IEXP / 64);
        k_swiglu_mma<true><<<g, 256, SW_SMEM, sB>>>();
    }
    {
        dim3 g(NEXP * 32, DMODEL / 128);
        k_down_mma<true><<<g, 256, DN_SMEM, sB>>>(nullptr);
    }
    k_combine<<<(T_TOK * DMODEL / 4 + 255) / 256, 256, 0, sB>>>(fused_out);
    cudaEventRecord(evJoin, sB);

    // ---- stream A continues: shared down-proj ------------------------------
    {
        dim3 g(T_TOK / 128, DMODEL / 128);
        k_down_mma<false><<<g, 256, DN_SMEM>>>(shared_out);
    }
    cudaStreamWaitEvent(0, evJoin, 0);
}